// round 6
// baseline (speedup 1.0000x reference)
#include <cuda_runtime.h>
#include <cstdint>

#define BT20   2621440u     // B*20 (elements per head slab)
#define NROWS  131072u
#define TPB    64
#define ATPB   256

__device__ uint32_t g_mask[40u * NROWS];   // bit o of word [k*NROWS+b] = keep(k,b,o)

// ---- packed f32x2 helpers ----
__device__ __forceinline__ unsigned long long pack2(float lo, float hi) {
    unsigned long long r;
    asm("mov.b64 %0, {%1, %2};" : "=l"(r) : "f"(lo), "f"(hi));
    return r;
}
__device__ __forceinline__ void unpack2(unsigned long long v, float &lo, float &hi) {
    asm("mov.b64 {%0, %1}, %2;" : "=f"(lo), "=f"(hi) : "l"(v));
}
__device__ __forceinline__ void fma2(unsigned long long &d, unsigned long long a,
                                     unsigned long long b) {
    asm("fma.rn.f32x2 %0, %1, %2, %0;" : "+l"(d) : "l"(a), "l"(b));
}
__device__ __forceinline__ unsigned long long f2lo(const float4 &v) { return pack2(v.x, v.y); }
__device__ __forceinline__ unsigned long long f2hi(const float4 &v) { return pack2(v.z, v.w); }

// integer add on the FMA pipe (IMAD); 'one' is runtime-opaque
__device__ __forceinline__ uint32_t addm(uint32_t a, uint32_t b, uint32_t one) {
    uint32_t r;
    asm("mad.lo.u32 %0, %1, %2, %3;" : "=r"(r) : "r"(b), "r"(one), "r"(a));
    return r;
}
__device__ __forceinline__ uint32_t mullo(uint32_t a, uint32_t b) {
    uint32_t r; asm("mul.lo.u32 %0, %1, %2;" : "=r"(r) : "r"(a), "r"(b)); return r;
}
__device__ __forceinline__ uint32_t mulhi_(uint32_t a, uint32_t b) {
    uint32_t r; asm("mul.hi.u32 %0, %1, %2;" : "=r"(r) : "r"(a), "r"(b)); return r;
}

// ---- Threefry-2x32-20, key (0,42); returns ~(o0^o1) ----
__device__ __forceinline__ uint32_t tf_xnor(uint32_t x1_init, uint32_t one, uint32_t c13) {
    const uint32_t ks1 = 42u;
    const uint32_t ks2 = 0x1BD11BDAu ^ 42u;
    uint32_t x0 = 0u;
    uint32_t x1 = x1_init;        // = j + ks1
#define TF_R(r)  { x0 = addm(x0, x1, one); \
                   x1 = __funnelshift_l(x1, x1, (r)); x1 ^= x0; }
#define TF_R13M  { x0 = addm(x0, x1, one); \
                   uint32_t lo_ = mullo(x1, c13), hi_ = mulhi_(x1, c13); \
                   x1 = (lo_ | hi_) ^ x0; }
    TF_R13M        TF_R(15) TF_R(26) TF_R(6)
    x0 = addm(x0, one*ks1, one);  x1 = addm(x1, one*(ks2 + 1u), one);
    TF_R(17) TF_R(29) TF_R(16) TF_R(24)
    x0 = addm(x0, one*ks2, one);  x1 = addm(x1, one*2u, one);
    TF_R13M        TF_R(15) TF_R(26) TF_R(6)
    x1 = addm(x1, one*(ks1 + 3u), one);
    TF_R(17) TF_R(29) TF_R(16) TF_R(24)
    x0 = addm(x0, one*ks1, one);  x1 = addm(x1, one*(ks2 + 4u), one);
    TF_R13M        TF_R(15) TF_R(26) TF_R(6)
    x0 = addm(x0, one*ks2, one);  x1 = addm(x1, one*5u, one);
#undef TF_R
#undef TF_R13M
    return ~(x0 ^ x1);   // keep-bit in MSB
}

// ================= Kernel A: mask generation =================
__global__ __launch_bounds__(ATPB)
void mask_kernel(uint32_t one) {
    const unsigned idx = blockIdx.x * ATPB + threadIdx.x;   // k*NROWS + b
    const unsigned k = idx >> 17;
    const unsigned b = idx & (NROWS - 1u);
    const uint32_t c13 = one << 13;
    const uint32_t jk = k * BT20 + b * 20u + 42u;           // j + ks1 base
    uint32_t w = 0u;
    #pragma unroll
    for (int o = 0; o < 20; o++) {
        uint32_t t = tf_xnor(addm(jk, one*(uint32_t)o, one), one, c13);
        uint32_t bit = t >> 31;
        asm("mad.lo.u32 %0, %1, %2, %0;" : "+r"(w) : "r"(bit), "r"(one << o));
    }
    g_mask[idx] = w;
}

// keep-multiplier 2.0f / 0.0f from mask bit o
__device__ __forceinline__ float keepf(uint32_t m, int o) {
    return __uint_as_float((uint32_t)((int)(m << (31 - o)) >> 31) & 0x40000000u);
}

// trunk for one row: h2[30] packed f32x2
__device__ __forceinline__ void trunk_row(const float* __restrict__ x, unsigned row,
                                          const float* sW1, const float* sb1,
                                          unsigned long long* h2) {
    unsigned long long x2[10];
    const float4* xp = (const float4*)(x + (size_t)row * 20);
    #pragma unroll
    for (int i = 0; i < 5; i++) {
        float4 v = xp[i];
        x2[2*i]   = f2lo(v);
        x2[2*i+1] = f2hi(v);
    }
    #pragma unroll
    for (int i = 0; i < 30; i++) {
        unsigned long long a0 = 0ull, a1 = 0ull;
        const float4* w0 = (const float4*)(sW1 + (2*i)   * 20);
        const float4* w1 = (const float4*)(sW1 + (2*i+1) * 20);
        #pragma unroll
        for (int d = 0; d < 5; d++) {
            float4 v0 = w0[d], v1 = w1[d];
            fma2(a0, x2[2*d],   f2lo(v0));
            fma2(a0, x2[2*d+1], f2hi(v0));
            fma2(a1, x2[2*d],   f2lo(v1));
            fma2(a1, x2[2*d+1], f2hi(v1));
        }
        float s0a, s0b, s1a, s1b;
        unpack2(a0, s0a, s0b);
        unpack2(a1, s1a, s1b);
        h2[i] = pack2(fmaxf(s0a + s0b + sb1[2*i],   0.f),
                      fmaxf(s1a + s1b + sb1[2*i+1], 0.f));
    }
}

// ================= Kernel B: fused MLP + mask apply (2 rows/thread) =========
__global__ __launch_bounds__(TPB, 6)
void mlp_kernel(const float* __restrict__ x,
                const float* __restrict__ W1,
                const float* __restrict__ b1,
                const float* __restrict__ Wh,
                const float* __restrict__ bh,
                float* __restrict__ out)
{
    __shared__ __align__(16) float sW1[1200];   // [60][20]
    __shared__           float sb1[64];
    __shared__ __align__(16) float sbh[800];    // [40][20]
    __shared__ __align__(16) float sWhA[1200];  // Wh[k]      [20][60]
    __shared__ __align__(16) float sWhB[1200];  // Wh[k+20]   [20][60]

    const int tid = threadIdx.x;

    for (int i = tid; i < 300; i += TPB)
        ((float4*)sW1)[i] = ((const float4*)W1)[i];
    for (int i = tid; i < 200; i += TPB)
        ((float4*)sbh)[i] = ((const float4*)bh)[i];
    if (tid < 60) sb1[tid] = b1[tid];
    __syncthreads();

    const unsigned b0 = blockIdx.x * 128u + (unsigned)tid;  // row 0
    const unsigned b1r = b0 + 64u;                          // row 1

    unsigned long long h2a[30], h2b[30];
    trunk_row(x, b0,  sW1, sb1, h2a);
    trunk_row(x, b1r, sW1, sb1, h2b);

    const unsigned baseA = b0  * 20u;
    const unsigned baseB = b1r * 20u;

    for (int k = 0; k < 20; k++) {
        // masks: [head A/B][row 0/1]
        const uint32_t mA0 = g_mask[(unsigned)k        * NROWS + b0];
        const uint32_t mA1 = g_mask[(unsigned)k        * NROWS + b1r];
        const uint32_t mB0 = g_mask[(unsigned)(k + 20) * NROWS + b0];
        const uint32_t mB1 = g_mask[(unsigned)(k + 20) * NROWS + b1r];

        __syncthreads();   // protect previous iteration's sWh reads
        const float4* srcA = (const float4*)(Wh + (size_t)k        * 1200);
        const float4* srcB = (const float4*)(Wh + (size_t)(k + 20) * 1200);
        for (int i = tid; i < 300; i += TPB) {
            ((float4*)sWhA)[i] = srcA[i];
            ((float4*)sWhB)[i] = srcB[i];
        }
        __syncthreads();

        #pragma unroll 1
        for (int oc = 0; oc < 5; oc++) {
            float yA0[4], yA1[4], yB0[4], yB1[4];
            #pragma unroll
            for (int u = 0; u < 4; u++) {
                const int o = oc * 4 + u;
                const float bA = sbh[k*20 + o];
                const float bB = sbh[(k+20)*20 + o];
                // ---- head A: one weight stream serves both rows ----
                {
                    const float4* w4 = (const float4*)(sWhA + o * 60);
                    unsigned long long ac0 = 0ull, ac1 = 0ull;
                    #pragma unroll
                    for (int d = 0; d < 15; d++) {
                        float4 v = w4[d];
                        unsigned long long lo = f2lo(v), hi = f2hi(v);
                        fma2(ac0, lo, h2a[2*d]);
                        fma2(ac0, hi, h2a[2*d+1]);
                        fma2(ac1, lo, h2b[2*d]);
                        fma2(ac1, hi, h2b[2*d+1]);
                    }
                    float p, q;
                    unpack2(ac0, p, q);
                    yA0[u] = fmaxf(p + q + bA, 0.f) * keepf(mA0, o);
                    unpack2(ac1, p, q);
                    yA1[u] = fmaxf(p + q + bA, 0.f) * keepf(mA1, o);
                }
                // ---- head B ----
                {
                    const float4* w4 = (const float4*)(sWhB + o * 60);
                    unsigned long long ac0 = 0ull, ac1 = 0ull;
                    #pragma unroll
                    for (int d = 0; d < 15; d++) {
                        float4 v = w4[d];
                        unsigned long long lo = f2lo(v), hi = f2hi(v);
                        fma2(ac0, lo, h2a[2*d]);
                        fma2(ac0, hi, h2a[2*d+1]);
                        fma2(ac1, lo, h2b[2*d]);
                        fma2(ac1, hi, h2b[2*d+1]);
                    }
                    float p, q;
                    unpack2(ac0, p, q);
                    yB0[u] = fmaxf(p + q + bB, 0.f) * keepf(mB0, o);
                    unpack2(ac1, p, q);
                    yB1[u] = fmaxf(p + q + bB, 0.f) * keepf(mB1, o);
                }
            }
            *(float4*)(out + (size_t)k        * BT20 + baseA + oc * 4) =
                make_float4(yA0[0], yA0[1], yA0[2], yA0[3]);
            *(float4*)(out + (size_t)k        * BT20 + baseB + oc * 4) =
                make_float4(yA1[0], yA1[1], yA1[2], yA1[3]);
            *(float4*)(out + (size_t)(k + 20) * BT20 + baseA + oc * 4) =
                make_float4(yB0[0], yB0[1], yB0[2], yB0[3]);
            *(float4*)(out + (size_t)(k + 20) * BT20 + baseB + oc * 4) =
                make_float4(yB1[0], yB1[1], yB1[2], yB1[3]);
        }
    }
}

extern "C" void kernel_launch(void* const* d_in, const int* in_sizes, int n_in,
                              void* d_out, int out_size) {
    const float* x  = (const float*)d_in[0];   // [131072, 20]
    const float* W1 = (const float*)d_in[1];   // [60, 20]
    const float* b1 = (const float*)d_in[2];   // [60]
    const float* Wh = (const float*)d_in[3];   // [40, 20, 60]
    const float* bh = (const float*)d_in[4];   // [40, 20]
    float* out = (float*)d_out;                // [40, 131072, 1, 20]

    const int rows = in_sizes[0] / 20;         // 131072
    mask_kernel<<<(40u * NROWS) / ATPB, ATPB>>>(1u);
    mlp_kernel<<<rows / 128, TPB>>>(x, W1, b1, Wh, bh, out);
}